// round 2
// baseline (speedup 1.0000x reference)
#include <cuda_runtime.h>
#include <cuda_bf16.h>
#include <cstdint>

// Problem constants: feature_matrix (64, 1, 1000, 128) fp32, T = 8
#define NB       64
#define PER_B    128000            // 1000*128 elements per batch
#define PER_B4   (PER_B / 4)       // 32000 float4 per batch
#define N_IN     (NB * PER_B)      // 8,192,000
#define N_IN4    (N_IN / 4)        // 2,097,152
#define TSTEPS   8

// ---------------------------------------------------------------------------
// Device scratch (no allocations allowed): per-batch min/max as ordered uints
// ---------------------------------------------------------------------------
__device__ unsigned g_min_ord[NB];
__device__ unsigned g_max_ord[NB];

__device__ __forceinline__ unsigned f2ord(float f) {
    unsigned u = __float_as_uint(f);
    return (u & 0x80000000u) ? ~u : (u | 0x80000000u);
}
__device__ __forceinline__ float ord2f(unsigned u) {
    u = (u & 0x80000000u) ? (u & 0x7FFFFFFFu) : ~u;
    return __uint_as_float(u);
}

__global__ void init_minmax_kernel() {
    int i = threadIdx.x;
    if (i < NB) {
        g_min_ord[i] = 0xFFFFFFFFu;
        g_max_ord[i] = 0u;
    }
}

// grid: (blocks_per_batch, NB), block: 256
__global__ void minmax_kernel(const float4* __restrict__ in) {
    const int b      = blockIdx.y;
    const int nblk   = gridDim.x;
    const int per_blk4 = PER_B4 / nblk;            // float4s per block (exact: 32000/16=2000)
    const float4* base = in + (size_t)b * PER_B4 + (size_t)blockIdx.x * per_blk4;

    float mn =  3.402823466e+38f;
    float mx = -3.402823466e+38f;
    for (int i = threadIdx.x; i < per_blk4; i += blockDim.x) {
        float4 v = base[i];
        mn = fminf(mn, fminf(fminf(v.x, v.y), fminf(v.z, v.w)));
        mx = fmaxf(mx, fmaxf(fmaxf(v.x, v.y), fmaxf(v.z, v.w)));
    }
    // warp reduce
    #pragma unroll
    for (int off = 16; off > 0; off >>= 1) {
        mn = fminf(mn, __shfl_xor_sync(0xFFFFFFFFu, mn, off));
        mx = fmaxf(mx, __shfl_xor_sync(0xFFFFFFFFu, mx, off));
    }
    __shared__ float smn[8], smx[8];
    int wid = threadIdx.x >> 5, lid = threadIdx.x & 31;
    if (lid == 0) { smn[wid] = mn; smx[wid] = mx; }
    __syncthreads();
    if (wid == 0) {
        mn = (lid < 8) ? smn[lid] :  3.402823466e+38f;
        mx = (lid < 8) ? smx[lid] : -3.402823466e+38f;
        #pragma unroll
        for (int off = 4; off > 0; off >>= 1) {
            mn = fminf(mn, __shfl_xor_sync(0xFFFFFFFFu, mn, off));
            mx = fmaxf(mx, __shfl_xor_sync(0xFFFFFFFFu, mx, off));
        }
        if (lid == 0) {
            atomicMin(&g_min_ord[b], f2ord(mn));
            atomicMax(&g_max_ord[b], f2ord(mx));
        }
    }
}

struct Thresh { float t[TSTEPS]; };

// One thread: 1 float4 in -> 8 float4 out (128 contiguous bytes)
__global__ void __launch_bounds__(256) encode_kernel(const float4* __restrict__ in,
                                                     float4* __restrict__ out,
                                                     Thresh th) {
    const int i = blockIdx.x * blockDim.x + threadIdx.x;   // exact grid: N_IN4 threads
    const int b = i / PER_B4;
    const float mn    = ord2f(g_min_ord[b]);
    const float range = __fsub_rn(ord2f(g_max_ord[b]), mn);

    const float4 x = in[i];
    float xs[4] = {x.x, x.y, x.z, x.w};
    float4 o[8];
    float* of = reinterpret_cast<float*>(o);
    #pragma unroll
    for (int j = 0; j < 4; j++) {
        // bit-exact match of reference: 8*(x-min)/(max-min), IEEE RN regardless of fast-math
        float norm = __fdiv_rn(__fmul_rn(8.0f, __fsub_rn(xs[j], mn)), range);
        #pragma unroll
        for (int t = 0; t < TSTEPS; t++)
            of[j * TSTEPS + t] = (norm > th.t[t]) ? 1.0f : 0.0f;
    }
    float4* dst = out + (size_t)i * 8;
    #pragma unroll
    for (int k = 0; k < 8; k++) dst[k] = o[k];
}

// ---------------------------------------------------------------------------
// Host: Threefry-2x32 to reproduce jax.random.permutation(jax.random.key(1), 8)
// under jax_threefry_partitionable=True (default since JAX 0.4.36):
//   - split (foldlike): key_i = threefry(key, (0, i)) full 64-bit output
//   - random_bits 32-bit: bits_i = out0 ^ out1 of threefry(subkey, (0, i))
// ---------------------------------------------------------------------------
static inline uint32_t rotl32(uint32_t x, int d) { return (x << d) | (x >> (32 - d)); }

static void threefry2x32(uint32_t k0, uint32_t k1, uint32_t x0, uint32_t x1,
                         uint32_t* o0, uint32_t* o1) {
    const int rotA[4] = {13, 15, 26, 6};
    const int rotB[4] = {17, 29, 16, 24};
    uint32_t ks0 = k0, ks1 = k1, ks2 = k0 ^ k1 ^ 0x1BD11BDAu;
    x0 += ks0; x1 += ks1;
    for (int i = 0; i < 4; i++) { x0 += x1; x1 = rotl32(x1, rotA[i]); x1 ^= x0; }
    x0 += ks1; x1 += ks2 + 1u;
    for (int i = 0; i < 4; i++) { x0 += x1; x1 = rotl32(x1, rotB[i]); x1 ^= x0; }
    x0 += ks2; x1 += ks0 + 2u;
    for (int i = 0; i < 4; i++) { x0 += x1; x1 = rotl32(x1, rotA[i]); x1 ^= x0; }
    x0 += ks0; x1 += ks1 + 3u;
    for (int i = 0; i < 4; i++) { x0 += x1; x1 = rotl32(x1, rotB[i]); x1 ^= x0; }
    x0 += ks1; x1 += ks2 + 4u;
    for (int i = 0; i < 4; i++) { x0 += x1; x1 = rotl32(x1, rotA[i]); x1 ^= x0; }
    x0 += ks2; x1 += ks0 + 5u;
    *o0 = x0; *o1 = x1;
}

extern "C" void kernel_launch(void* const* d_in, const int* in_sizes, int n_in,
                              void* d_out, int out_size) {
    // key(1) -> threefry key data (0, 1)
    // split(key) foldlike: keys from 64-bit iota counters (hi,lo) = (0,0),(0,1)
    //   key, subkey = split(key)  ->  subkey = threefry((0,1), (0,1))
    uint32_t sk0, sk1;
    threefry2x32(0u, 1u, 0u, 1u, &sk0, &sk1);
    // random_bits(subkey, 32, (8,)) partitionable: counter (0, i), bits = o0 ^ o1
    uint32_t keys[8];
    for (int i = 0; i < 8; i++) {
        uint32_t o0, o1;
        threefry2x32(sk0, sk1, 0u, (uint32_t)i, &o0, &o1);
        keys[i] = o0 ^ o1;
    }
    // stable argsort ascending (lax.sort_key_val) -> perm
    int perm[8] = {0, 1, 2, 3, 4, 5, 6, 7};
    for (int i = 1; i < 8; i++) {           // stable insertion sort
        uint32_t kv = keys[perm[i]];
        int p = perm[i], j = i - 1;
        while (j >= 0 && keys[perm[j]] > kv) { perm[j + 1] = perm[j]; j--; }
        perm[j + 1] = p;
    }
    Thresh th;
    for (int i = 0; i < 8; i++) th.t[i] = (float)perm[i];

    const float4* in  = (const float4*)d_in[0];
    float4*       out = (float4*)d_out;

    init_minmax_kernel<<<1, 64>>>();
    dim3 rgrid(16, NB);
    minmax_kernel<<<rgrid, 256>>>(in);
    encode_kernel<<<N_IN4 / 256, 256>>>(in, out, th);
}

// round 4
// speedup vs baseline: 1.4389x; 1.4389x over previous
#include <cuda_runtime.h>
#include <cuda_bf16.h>
#include <cstdint>

// Problem: feature_matrix (64, 1, 1000, 128) fp32 -> out (64, 1, 1000, 128, 8) fp32
#define NB        64
#define PER_B     128000                 // elements per batch
#define PER_B4    (PER_B / 4)            // 32000 float4 per batch (input)
#define N_IN      (NB * PER_B)           // 8,192,000 input floats
#define TSTEPS    8
#define RBLK      16                     // reduce blocks per batch
#define EBLOCKS_PER_B 500                // encode blocks per batch (512 out-float4 each)

// ---------------------------------------------------------------------------
// Device scratch: per-(batch, block) partial min/max. Plain stores -> no init
// kernel, no atomics, deterministic across graph replays.
// ---------------------------------------------------------------------------
__device__ float g_part_min[NB * RBLK];
__device__ float g_part_max[NB * RBLK];

// grid: (RBLK, NB), block: 256. Writes one partial min/max per block.
__global__ void __launch_bounds__(256) minmax_kernel(const float4* __restrict__ in) {
    const int b = blockIdx.y;
    const int per_blk4 = PER_B4 / RBLK;                       // 2000
    const float4* base = in + (size_t)b * PER_B4 + (size_t)blockIdx.x * per_blk4;

    float mn =  3.402823466e+38f;
    float mx = -3.402823466e+38f;
    for (int i = threadIdx.x; i < per_blk4; i += blockDim.x) {
        float4 v = base[i];
        mn = fminf(mn, fminf(fminf(v.x, v.y), fminf(v.z, v.w)));
        mx = fmaxf(mx, fmaxf(fmaxf(v.x, v.y), fmaxf(v.z, v.w)));
    }
    #pragma unroll
    for (int off = 16; off > 0; off >>= 1) {
        mn = fminf(mn, __shfl_xor_sync(0xFFFFFFFFu, mn, off));
        mx = fmaxf(mx, __shfl_xor_sync(0xFFFFFFFFu, mx, off));
    }
    __shared__ float smn[8], smx[8];
    int wid = threadIdx.x >> 5, lid = threadIdx.x & 31;
    if (lid == 0) { smn[wid] = mn; smx[wid] = mx; }
    __syncthreads();
    if (threadIdx.x == 0) {
        mn = smn[0]; mx = smx[0];
        #pragma unroll
        for (int w = 1; w < 8; w++) { mn = fminf(mn, smn[w]); mx = fmaxf(mx, smx[w]); }
        g_part_min[b * RBLK + blockIdx.x] = mn;
        g_part_max[b * RBLK + blockIdx.x] = mx;
    }
}

struct Thresh { float t[TSTEPS]; };

// One thread -> 2 output float4 slots, warp-contiguous stores (full 32B sectors,
// 512B per warp STG) instead of the 128B-thread-stride pattern that made R2's
// write stream half-sector.
// Slot s covers output floats [4s, 4s+4) = element (s>>1), time-half (s&1).
// grid: 32000 blocks x 256 threads; each block = 512 slots = 256 elements.
__global__ void __launch_bounds__(256) encode_kernel(const float* __restrict__ in,
                                                     float4* __restrict__ out,
                                                     Thresh th) {
    const int tid = threadIdx.x;
    const int b   = blockIdx.x / EBLOCKS_PER_B;

    // Fold the 16 per-batch partials (L2-resident) into final min/range.
    __shared__ float s_mn, s_mx;
    if (tid < 32) {
        float pmn = (tid < RBLK) ? g_part_min[b * RBLK + tid] :  3.402823466e+38f;
        float pmx = (tid < RBLK) ? g_part_max[b * RBLK + tid] : -3.402823466e+38f;
        #pragma unroll
        for (int off = 8; off > 0; off >>= 1) {
            pmn = fminf(pmn, __shfl_xor_sync(0xFFFFFFFFu, pmn, off));
            pmx = fmaxf(pmx, __shfl_xor_sync(0xFFFFFFFFu, pmx, off));
        }
        if (tid == 0) { s_mn = pmn; s_mx = pmx; }
    }
    __syncthreads();
    const float mn    = s_mn;
    const float range = __fsub_rn(s_mx, mn);

    // Both of this thread's slots have the same parity (tid&1): pick half once.
    const bool hi = (tid & 1);
    const float4 tv = hi ? make_float4(th.t[4], th.t[5], th.t[6], th.t[7])
                         : make_float4(th.t[0], th.t[1], th.t[2], th.t[3]);

    const int base_s = blockIdx.x * 512 + tid;
    #pragma unroll
    for (int k = 0; k < 2; k++) {
        const int s = base_s + k * 256;
        const float x = __ldg(in + (s >> 1));
        // bit-exact vs reference: 8*(x-min)/(max-min), IEEE RN
        const float norm = __fdiv_rn(__fmul_rn(8.0f, __fsub_rn(x, mn)), range);
        float4 o;
        o.x = (norm > tv.x) ? 1.0f : 0.0f;
        o.y = (norm > tv.y) ? 1.0f : 0.0f;
        o.z = (norm > tv.z) ? 1.0f : 0.0f;
        o.w = (norm > tv.w) ? 1.0f : 0.0f;
        out[s] = o;
    }
}

// ---------------------------------------------------------------------------
// Host: Threefry-2x32, jax.random.permutation(key(1), 8) with
// jax_threefry_partitionable=True semantics (verified rel_err=0 in R2):
//   split (foldlike): subkey = threefry(key, (0, 1))
//   random_bits 32-bit: bits_i = out0 ^ out1 of threefry(subkey, (0, i))
// ---------------------------------------------------------------------------
static inline uint32_t rotl32(uint32_t x, int d) { return (x << d) | (x >> (32 - d)); }

static void threefry2x32(uint32_t k0, uint32_t k1, uint32_t x0, uint32_t x1,
                         uint32_t* o0, uint32_t* o1) {
    const int rotA[4] = {13, 15, 26, 6};
    const int rotB[4] = {17, 29, 16, 24};
    uint32_t ks0 = k0, ks1 = k1, ks2 = k0 ^ k1 ^ 0x1BD11BDAu;
    x0 += ks0; x1 += ks1;
    for (int i = 0; i < 4; i++) { x0 += x1; x1 = rotl32(x1, rotA[i]); x1 ^= x0; }
    x0 += ks1; x1 += ks2 + 1u;
    for (int i = 0; i < 4; i++) { x0 += x1; x1 = rotl32(x1, rotB[i]); x1 ^= x0; }
    x0 += ks2; x1 += ks0 + 2u;
    for (int i = 0; i < 4; i++) { x0 += x1; x1 = rotl32(x1, rotA[i]); x1 ^= x0; }
    x0 += ks0; x1 += ks1 + 3u;
    for (int i = 0; i < 4; i++) { x0 += x1; x1 = rotl32(x1, rotB[i]); x1 ^= x0; }
    x0 += ks1; x1 += ks2 + 4u;
    for (int i = 0; i < 4; i++) { x0 += x1; x1 = rotl32(x1, rotA[i]); x1 ^= x0; }
    x0 += ks2; x1 += ks0 + 5u;
    *o0 = x0; *o1 = x1;
}

extern "C" void kernel_launch(void* const* d_in, const int* in_sizes, int n_in,
                              void* d_out, int out_size) {
    uint32_t sk0, sk1;
    threefry2x32(0u, 1u, 0u, 1u, &sk0, &sk1);
    uint32_t keys[8];
    for (int i = 0; i < 8; i++) {
        uint32_t o0, o1;
        threefry2x32(sk0, sk1, 0u, (uint32_t)i, &o0, &o1);
        keys[i] = o0 ^ o1;
    }
    int perm[8] = {0, 1, 2, 3, 4, 5, 6, 7};
    for (int i = 1; i < 8; i++) {           // stable insertion sort (ascending)
        uint32_t kv = keys[perm[i]];
        int p = perm[i], j = i - 1;
        while (j >= 0 && keys[perm[j]] > kv) { perm[j + 1] = perm[j]; j--; }
        perm[j + 1] = p;
    }
    Thresh th;
    for (int i = 0; i < 8; i++) th.t[i] = (float)perm[i];

    const float* in_f = (const float*)d_in[0];

    dim3 rgrid(RBLK, NB);
    minmax_kernel<<<rgrid, 256>>>((const float4*)in_f);
    encode_kernel<<<NB * EBLOCKS_PER_B, 256>>>(in_f, (float4*)d_out, th);
}

// round 5
// speedup vs baseline: 1.4742x; 1.0245x over previous
#include <cuda_runtime.h>
#include <cuda_bf16.h>
#include <cstdint>

// Problem: feature_matrix (64, 1, 1000, 128) fp32 -> out (64, 1, 1000, 128, 8) fp32
#define NB        64
#define PER_B     128000                 // elements per batch
#define PER_B4    (PER_B / 4)            // 32000 float4 per batch (input)
#define N_IN      (NB * PER_B)           // 8,192,000 input floats
#define TSTEPS    8
#define RBLK      16                     // reduce blocks per batch
#define EBLOCKS_PER_B 250                // encode blocks per batch (1024 out-float4 each)

// ---------------------------------------------------------------------------
// Device scratch: per-(batch, block) partial min/max + per-batch cut values.
// Plain stores, no init kernel, no atomics, deterministic across replays.
// ---------------------------------------------------------------------------
__device__ float  g_part_min[NB * RBLK];
__device__ float  g_part_max[NB * RBLK];
__device__ float4 g_cuts4[NB * 2];       // [b][parity]: cuts for out positions 0-3 / 4-7

__device__ __forceinline__ unsigned f2ord(float f) {
    unsigned u = __float_as_uint(f);
    return (u & 0x80000000u) ? ~u : (u | 0x80000000u);
}
__device__ __forceinline__ float ord2f(unsigned u) {
    u = (u & 0x80000000u) ? (u & 0x7FFFFFFFu) : ~u;
    return __uint_as_float(u);
}

// grid: (RBLK, NB), block: 256. One partial min/max per block.
__global__ void __launch_bounds__(256) minmax_kernel(const float4* __restrict__ in) {
    const int b = blockIdx.y;
    const int per_blk4 = PER_B4 / RBLK;                       // 2000
    const float4* base = in + (size_t)b * PER_B4 + (size_t)blockIdx.x * per_blk4;

    float mn =  3.402823466e+38f;
    float mx = -3.402823466e+38f;
    for (int i = threadIdx.x; i < per_blk4; i += blockDim.x) {
        float4 v = base[i];
        mn = fminf(mn, fminf(fminf(v.x, v.y), fminf(v.z, v.w)));
        mx = fmaxf(mx, fmaxf(fmaxf(v.x, v.y), fmaxf(v.z, v.w)));
    }
    #pragma unroll
    for (int off = 16; off > 0; off >>= 1) {
        mn = fminf(mn, __shfl_xor_sync(0xFFFFFFFFu, mn, off));
        mx = fmaxf(mx, __shfl_xor_sync(0xFFFFFFFFu, mx, off));
    }
    __shared__ float smn[8], smx[8];
    int wid = threadIdx.x >> 5, lid = threadIdx.x & 31;
    if (lid == 0) { smn[wid] = mn; smx[wid] = mx; }
    __syncthreads();
    if (threadIdx.x == 0) {
        mn = smn[0]; mx = smx[0];
        #pragma unroll
        for (int w = 1; w < 8; w++) { mn = fminf(mn, smn[w]); mx = fmaxf(mx, smx[w]); }
        g_part_min[b * RBLK + blockIdx.x] = mn;
        g_part_max[b * RBLK + blockIdx.x] = mx;
    }
}

struct Thresh { float t[TSTEPS]; };

// 1 block, 512 threads = 64 batches x 8 output positions.
// Computes X = max{x in [mn,mx] : RN(RN(8*RN(x-mn))/range) <= t} by binary
// search over ordered-float bits, with the EXACT hot-loop formula of the
// reference (IEEE RN). Monotonicity of RN stages makes (norm > t) <=> (x > X)
// bit-identical for every input in [mn, mx].
__global__ void __launch_bounds__(512) cuts_kernel(Thresh th) {
    const int b = threadIdx.x >> 3;      // 0..63
    const int j = threadIdx.x & 7;       // output time position 0..7

    float mn =  3.402823466e+38f;
    float mx = -3.402823466e+38f;
    #pragma unroll
    for (int i = 0; i < RBLK; i++) {
        mn = fminf(mn, g_part_min[b * RBLK + i]);
        mx = fmaxf(mx, g_part_max[b * RBLK + i]);
    }
    const float range = __fsub_rn(mx, mn);
    const float t = th.t[j];             // threshold for this output position

    unsigned lo = f2ord(mn), hi = f2ord(mx);   // invariant: f(lo) <= t (f(mn)=0)
    while (lo < hi) {
        unsigned mid = lo + ((hi - lo + 1u) >> 1);
        float x = ord2f(mid);
        float norm = __fdiv_rn(__fmul_rn(8.0f, __fsub_rn(x, mn)), range);
        if (norm <= t) lo = mid; else hi = mid - 1u;
    }
    reinterpret_cast<float*>(g_cuts4)[b * 8 + j] = ord2f(lo);
}

// One thread -> 4 output float4 slots (warp-contiguous 512B stores, full
// sectors). Slot s = element (s>>1), time-half (s&1). Per slot: 1 LDG, 4
// compares, 1 STG.128. No divide, no smem, no syncthreads.
// grid: 16000 blocks x 256 threads; block covers 1024 slots = 512 elements.
__global__ void __launch_bounds__(256) encode_kernel(const float* __restrict__ in,
                                                     float4* __restrict__ out) {
    const int tid = threadIdx.x;
    const int b   = blockIdx.x / EBLOCKS_PER_B;
    // Both-parity threads read a uniform-per-(block,parity) float4 of cuts.
    const float4 cut = g_cuts4[b * 2 + (tid & 1)];

    const int base_s = blockIdx.x * 1024 + tid;
    #pragma unroll
    for (int k = 0; k < 4; k++) {
        const int s = base_s + k * 256;
        const float x = __ldg(in + (s >> 1));
        float4 o;
        o.x = (x > cut.x) ? 1.0f : 0.0f;
        o.y = (x > cut.y) ? 1.0f : 0.0f;
        o.z = (x > cut.z) ? 1.0f : 0.0f;
        o.w = (x > cut.w) ? 1.0f : 0.0f;
        out[s] = o;
    }
}

// ---------------------------------------------------------------------------
// Host: Threefry-2x32, jax.random.permutation(key(1), 8) with
// jax_threefry_partitionable=True semantics (verified rel_err=0 in R2/R4):
//   split (foldlike): subkey = threefry(key, (0, 1))
//   random_bits 32-bit: bits_i = out0 ^ out1 of threefry(subkey, (0, i))
// ---------------------------------------------------------------------------
static inline uint32_t rotl32(uint32_t x, int d) { return (x << d) | (x >> (32 - d)); }

static void threefry2x32(uint32_t k0, uint32_t k1, uint32_t x0, uint32_t x1,
                         uint32_t* o0, uint32_t* o1) {
    const int rotA[4] = {13, 15, 26, 6};
    const int rotB[4] = {17, 29, 16, 24};
    uint32_t ks0 = k0, ks1 = k1, ks2 = k0 ^ k1 ^ 0x1BD11BDAu;
    x0 += ks0; x1 += ks1;
    for (int i = 0; i < 4; i++) { x0 += x1; x1 = rotl32(x1, rotA[i]); x1 ^= x0; }
    x0 += ks1; x1 += ks2 + 1u;
    for (int i = 0; i < 4; i++) { x0 += x1; x1 = rotl32(x1, rotB[i]); x1 ^= x0; }
    x0 += ks2; x1 += ks0 + 2u;
    for (int i = 0; i < 4; i++) { x0 += x1; x1 = rotl32(x1, rotA[i]); x1 ^= x0; }
    x0 += ks0; x1 += ks1 + 3u;
    for (int i = 0; i < 4; i++) { x0 += x1; x1 = rotl32(x1, rotB[i]); x1 ^= x0; }
    x0 += ks1; x1 += ks2 + 4u;
    for (int i = 0; i < 4; i++) { x0 += x1; x1 = rotl32(x1, rotA[i]); x1 ^= x0; }
    x0 += ks2; x1 += ks0 + 5u;
    *o0 = x0; *o1 = x1;
}

extern "C" void kernel_launch(void* const* d_in, const int* in_sizes, int n_in,
                              void* d_out, int out_size) {
    uint32_t sk0, sk1;
    threefry2x32(0u, 1u, 0u, 1u, &sk0, &sk1);
    uint32_t keys[8];
    for (int i = 0; i < 8; i++) {
        uint32_t o0, o1;
        threefry2x32(sk0, sk1, 0u, (uint32_t)i, &o0, &o1);
        keys[i] = o0 ^ o1;
    }
    int perm[8] = {0, 1, 2, 3, 4, 5, 6, 7};
    for (int i = 1; i < 8; i++) {           // stable insertion sort (ascending)
        uint32_t kv = keys[perm[i]];
        int p = perm[i], j = i - 1;
        while (j >= 0 && keys[perm[j]] > kv) { perm[j + 1] = perm[j]; j--; }
        perm[j + 1] = p;
    }
    Thresh th;
    for (int i = 0; i < 8; i++) th.t[i] = (float)perm[i];

    const float* in_f = (const float*)d_in[0];

    dim3 rgrid(RBLK, NB);
    minmax_kernel<<<rgrid, 256>>>((const float4*)in_f);
    cuts_kernel<<<1, 512>>>(th);
    encode_kernel<<<NB * EBLOCKS_PER_B, 256>>>(in_f, (float4*)d_out);
}

// round 6
// speedup vs baseline: 1.6144x; 1.0951x over previous
#include <cuda_runtime.h>
#include <cuda_bf16.h>
#include <cstdint>

// Problem: feature_matrix (64, 1, 1000, 128) fp32 -> out (64, 1, 1000, 128, 8) fp32
#define NB        64
#define PER_B     128000                 // elements per batch
#define PER_B4    (PER_B / 4)            // 32000 float4 per batch (input)
#define TSTEPS    8
#define RBLK      25                     // reduce blocks per batch (1280 f4 each)
#define RB_F4     1280                   // float4 per reduce block = 5 * 256
#define EBLOCKS_PER_B 125                // encode blocks per batch (2048 out-float4 each)

// ---------------------------------------------------------------------------
// Device scratch: per-(batch, block) partial min/max + per-batch cut values.
// Plain stores, no init kernel, no atomics, deterministic across replays.
// ---------------------------------------------------------------------------
__device__ float  g_part_min[NB * RBLK];
__device__ float  g_part_max[NB * RBLK];
__device__ float4 g_cuts4[NB * 2];       // [b][parity]: cuts for out positions 0-3 / 4-7

__device__ __forceinline__ unsigned f2ord(float f) {
    unsigned u = __float_as_uint(f);
    return (u & 0x80000000u) ? ~u : (u | 0x80000000u);
}
__device__ __forceinline__ float ord2f(unsigned u) {
    u = (u & 0x80000000u) ? (u & 0x7FFFFFFFu) : ~u;
    return __uint_as_float(u);
}

// grid: (RBLK, NB), block: 256. 5 independent front-batched LDG.128 per thread
// (max MLP, no dependent min/max chain between loads), then tree reduce.
__global__ void __launch_bounds__(256) minmax_kernel(const float4* __restrict__ in) {
    const int b = blockIdx.y;
    const float4* base = in + (size_t)b * PER_B4 + (size_t)blockIdx.x * RB_F4;

    float4 v0 = base[threadIdx.x];
    float4 v1 = base[threadIdx.x + 256];
    float4 v2 = base[threadIdx.x + 512];
    float4 v3 = base[threadIdx.x + 768];
    float4 v4 = base[threadIdx.x + 1024];

    float mn0 = fminf(fminf(v0.x, v0.y), fminf(v0.z, v0.w));
    float mx0 = fmaxf(fmaxf(v0.x, v0.y), fmaxf(v0.z, v0.w));
    float mn1 = fminf(fminf(v1.x, v1.y), fminf(v1.z, v1.w));
    float mx1 = fmaxf(fmaxf(v1.x, v1.y), fmaxf(v1.z, v1.w));
    float mn2 = fminf(fminf(v2.x, v2.y), fminf(v2.z, v2.w));
    float mx2 = fmaxf(fmaxf(v2.x, v2.y), fmaxf(v2.z, v2.w));
    float mn3 = fminf(fminf(v3.x, v3.y), fminf(v3.z, v3.w));
    float mx3 = fmaxf(fmaxf(v3.x, v3.y), fmaxf(v3.z, v3.w));
    float mn4 = fminf(fminf(v4.x, v4.y), fminf(v4.z, v4.w));
    float mx4 = fmaxf(fmaxf(v4.x, v4.y), fmaxf(v4.z, v4.w));

    float mn = fminf(fminf(fminf(mn0, mn1), fminf(mn2, mn3)), mn4);
    float mx = fmaxf(fmaxf(fmaxf(mx0, mx1), fmaxf(mx2, mx3)), mx4);

    #pragma unroll
    for (int off = 16; off > 0; off >>= 1) {
        mn = fminf(mn, __shfl_xor_sync(0xFFFFFFFFu, mn, off));
        mx = fmaxf(mx, __shfl_xor_sync(0xFFFFFFFFu, mx, off));
    }
    __shared__ float smn[8], smx[8];
    int wid = threadIdx.x >> 5, lid = threadIdx.x & 31;
    if (lid == 0) { smn[wid] = mn; smx[wid] = mx; }
    __syncthreads();
    if (threadIdx.x == 0) {
        mn = smn[0]; mx = smx[0];
        #pragma unroll
        for (int w = 1; w < 8; w++) { mn = fminf(mn, smn[w]); mx = fmaxf(mx, smx[w]); }
        g_part_min[b * RBLK + blockIdx.x] = mn;
        g_part_max[b * RBLK + blockIdx.x] = mx;
    }
}

struct Thresh { float t[TSTEPS]; };

// 1 block, 512 threads = 64 batches x 8 output positions.
// X = max{x in [mn,mx] : RN(RN(8*RN(x-mn))/range) <= t}, binary search over
// ordered-float bits with the reference's exact IEEE-RN formula; monotone RN
// stages make (norm > t) <=> (x > X) bit-identical on [mn, mx].
__global__ void __launch_bounds__(512) cuts_kernel(Thresh th) {
    const int b = threadIdx.x >> 3;      // 0..63
    const int j = threadIdx.x & 7;       // output time position 0..7

    float mn =  3.402823466e+38f;
    float mx = -3.402823466e+38f;
    #pragma unroll
    for (int i = 0; i < RBLK; i++) {
        mn = fminf(mn, g_part_min[b * RBLK + i]);
        mx = fmaxf(mx, g_part_max[b * RBLK + i]);
    }
    const float range = __fsub_rn(mx, mn);
    const float t = th.t[j];

    unsigned lo = f2ord(mn), hi = f2ord(mx);   // invariant: f(lo) <= t (f(mn)=0)
    while (lo < hi) {
        unsigned mid = lo + ((hi - lo + 1u) >> 1);
        float x = ord2f(mid);
        float norm = __fdiv_rn(__fmul_rn(8.0f, __fsub_rn(x, mn)), range);
        if (norm <= t) lo = mid; else hi = mid - 1u;
    }
    reinterpret_cast<float*>(g_cuts4)[b * 8 + j] = ord2f(lo);
}

// One thread -> 8 output float4 slots (warp-contiguous 512B stores, full
// sectors). Slot s = element (s>>1), time-half (s&1). Streaming stores keep
// the 32MB input L2-resident (loaded by minmax) so encode reads hit L2.
// grid: 8000 blocks x 256 threads; block covers 2048 slots = 1024 elements.
__global__ void __launch_bounds__(256) encode_kernel(const float* __restrict__ in,
                                                     float4* __restrict__ out) {
    const int tid = threadIdx.x;
    const int b   = blockIdx.x / EBLOCKS_PER_B;
    const float4 cut = g_cuts4[b * 2 + (tid & 1)];

    const int base_s = blockIdx.x * 2048 + tid;
    #pragma unroll
    for (int k = 0; k < 8; k++) {
        const int s = base_s + k * 256;
        const float x = __ldg(in + (s >> 1));
        float4 o;
        o.x = (x > cut.x) ? 1.0f : 0.0f;
        o.y = (x > cut.y) ? 1.0f : 0.0f;
        o.z = (x > cut.z) ? 1.0f : 0.0f;
        o.w = (x > cut.w) ? 1.0f : 0.0f;
        __stcs(out + s, o);              // evict-first: don't flush input from L2
    }
}

// ---------------------------------------------------------------------------
// Host: Threefry-2x32, jax.random.permutation(key(1), 8) with
// jax_threefry_partitionable=True semantics (verified rel_err=0 in R2/R4/R5):
//   split (foldlike): subkey = threefry(key, (0, 1))
//   random_bits 32-bit: bits_i = out0 ^ out1 of threefry(subkey, (0, i))
// ---------------------------------------------------------------------------
static inline uint32_t rotl32(uint32_t x, int d) { return (x << d) | (x >> (32 - d)); }

static void threefry2x32(uint32_t k0, uint32_t k1, uint32_t x0, uint32_t x1,
                         uint32_t* o0, uint32_t* o1) {
    const int rotA[4] = {13, 15, 26, 6};
    const int rotB[4] = {17, 29, 16, 24};
    uint32_t ks0 = k0, ks1 = k1, ks2 = k0 ^ k1 ^ 0x1BD11BDAu;
    x0 += ks0; x1 += ks1;
    for (int i = 0; i < 4; i++) { x0 += x1; x1 = rotl32(x1, rotA[i]); x1 ^= x0; }
    x0 += ks1; x1 += ks2 + 1u;
    for (int i = 0; i < 4; i++) { x0 += x1; x1 = rotl32(x1, rotB[i]); x1 ^= x0; }
    x0 += ks2; x1 += ks0 + 2u;
    for (int i = 0; i < 4; i++) { x0 += x1; x1 = rotl32(x1, rotA[i]); x1 ^= x0; }
    x0 += ks0; x1 += ks1 + 3u;
    for (int i = 0; i < 4; i++) { x0 += x1; x1 = rotl32(x1, rotB[i]); x1 ^= x0; }
    x0 += ks1; x1 += ks2 + 4u;
    for (int i = 0; i < 4; i++) { x0 += x1; x1 = rotl32(x1, rotA[i]); x1 ^= x0; }
    x0 += ks2; x1 += ks0 + 5u;
    *o0 = x0; *o1 = x1;
}

extern "C" void kernel_launch(void* const* d_in, const int* in_sizes, int n_in,
                              void* d_out, int out_size) {
    uint32_t sk0, sk1;
    threefry2x32(0u, 1u, 0u, 1u, &sk0, &sk1);
    uint32_t keys[8];
    for (int i = 0; i < 8; i++) {
        uint32_t o0, o1;
        threefry2x32(sk0, sk1, 0u, (uint32_t)i, &o0, &o1);
        keys[i] = o0 ^ o1;
    }
    int perm[8] = {0, 1, 2, 3, 4, 5, 6, 7};
    for (int i = 1; i < 8; i++) {           // stable insertion sort (ascending)
        uint32_t kv = keys[perm[i]];
        int p = perm[i], j = i - 1;
        while (j >= 0 && keys[perm[j]] > kv) { perm[j + 1] = perm[j]; j--; }
        perm[j + 1] = p;
    }
    Thresh th;
    for (int i = 0; i < 8; i++) th.t[i] = (float)perm[i];

    const float* in_f = (const float*)d_in[0];

    dim3 rgrid(RBLK, NB);
    minmax_kernel<<<rgrid, 256>>>((const float4*)in_f);
    cuts_kernel<<<1, 512>>>(th);
    encode_kernel<<<NB * EBLOCKS_PER_B, 256>>>(in_f, (float4*)d_out);
}

// round 7
// speedup vs baseline: 1.6248x; 1.0065x over previous
#include <cuda_runtime.h>
#include <cuda_bf16.h>
#include <cstdint>

// Problem: feature_matrix (64, 1, 1000, 128) fp32 -> out (64, 1, 1000, 128, 8) fp32
#define NB        64
#define PER_B     128000                 // elements per batch
#define PER_B4    (PER_B / 4)            // 32000 float4 per batch (input)
#define TSTEPS    8
#define RBLK      5                      // reduce blocks per batch
#define RB_F4     6400                   // float4 per reduce block = 5 iters * 5 * 256
#define EBLOCKS_PER_B 125                // encode blocks per batch (2048 out-float4 each)

// ---------------------------------------------------------------------------
// Device scratch: per-(batch, block) partial min/max + per-batch cut values.
// Plain stores, no init kernel, no atomics, deterministic across replays.
// ---------------------------------------------------------------------------
__device__ float  g_part_min[NB * RBLK];
__device__ float  g_part_max[NB * RBLK];
__device__ float4 g_cuts4[NB * 2];       // [b][parity]: cuts for out positions 0-3 / 4-7

__device__ __forceinline__ unsigned f2ord(float f) {
    unsigned u = __float_as_uint(f);
    return (u & 0x80000000u) ? ~u : (u | 0x80000000u);
}
__device__ __forceinline__ float ord2f(unsigned u) {
    u = (u & 0x80000000u) ? (u & 0x7FFFFFFFu) : ~u;
    return __uint_as_float(u);
}

// grid: (RBLK, NB), block: 256. Each block: 6400 float4 (100KB) in 5 loop
// iterations of 5 front-batched independent LDG.128 per thread. Amortizes the
// reduce epilogue over 5x more data than R6 (which spent it every 20KB).
__global__ void __launch_bounds__(256) minmax_kernel(const float4* __restrict__ in) {
    const int b = blockIdx.y;
    const float4* base = in + (size_t)b * PER_B4 + (size_t)blockIdx.x * RB_F4
                            + threadIdx.x;

    float mn =  3.402823466e+38f;
    float mx = -3.402823466e+38f;
    #pragma unroll
    for (int it = 0; it < 5; it++) {
        // 5 independent loads, front-batched (no dependent ops between them)
        float4 v0 = base[it * 1280 +    0];
        float4 v1 = base[it * 1280 +  256];
        float4 v2 = base[it * 1280 +  512];
        float4 v3 = base[it * 1280 +  768];
        float4 v4 = base[it * 1280 + 1024];

        float a0 = fminf(fminf(v0.x, v0.y), fminf(v0.z, v0.w));
        float b0 = fmaxf(fmaxf(v0.x, v0.y), fmaxf(v0.z, v0.w));
        float a1 = fminf(fminf(v1.x, v1.y), fminf(v1.z, v1.w));
        float b1 = fmaxf(fmaxf(v1.x, v1.y), fmaxf(v1.z, v1.w));
        float a2 = fminf(fminf(v2.x, v2.y), fminf(v2.z, v2.w));
        float b2 = fmaxf(fmaxf(v2.x, v2.y), fmaxf(v2.z, v2.w));
        float a3 = fminf(fminf(v3.x, v3.y), fminf(v3.z, v3.w));
        float b3 = fmaxf(fmaxf(v3.x, v3.y), fmaxf(v3.z, v3.w));
        float a4 = fminf(fminf(v4.x, v4.y), fminf(v4.z, v4.w));
        float b4 = fmaxf(fmaxf(v4.x, v4.y), fmaxf(v4.z, v4.w));

        mn = fminf(mn, fminf(fminf(fminf(a0, a1), fminf(a2, a3)), a4));
        mx = fmaxf(mx, fmaxf(fmaxf(fmaxf(b0, b1), fmaxf(b2, b3)), b4));
    }

    #pragma unroll
    for (int off = 16; off > 0; off >>= 1) {
        mn = fminf(mn, __shfl_xor_sync(0xFFFFFFFFu, mn, off));
        mx = fmaxf(mx, __shfl_xor_sync(0xFFFFFFFFu, mx, off));
    }
    __shared__ float smn[8], smx[8];
    int wid = threadIdx.x >> 5, lid = threadIdx.x & 31;
    if (lid == 0) { smn[wid] = mn; smx[wid] = mx; }
    __syncthreads();
    if (threadIdx.x == 0) {
        mn = smn[0]; mx = smx[0];
        #pragma unroll
        for (int w = 1; w < 8; w++) { mn = fminf(mn, smn[w]); mx = fmaxf(mx, smx[w]); }
        g_part_min[b * RBLK + blockIdx.x] = mn;
        g_part_max[b * RBLK + blockIdx.x] = mx;
    }
}

struct Thresh { float t[TSTEPS]; };

// 1 block, 512 threads = 64 batches x 8 output positions.
// X = max{x in [mn,mx] : RN(RN(8*RN(x-mn))/range) <= t}, binary search over
// ordered-float bits with the reference's exact IEEE-RN formula; monotone RN
// stages make (norm > t) <=> (x > X) bit-identical on [mn, mx].
__global__ void __launch_bounds__(512) cuts_kernel(Thresh th) {
    const int b = threadIdx.x >> 3;      // 0..63
    const int j = threadIdx.x & 7;       // output time position 0..7

    float mn =  3.402823466e+38f;
    float mx = -3.402823466e+38f;
    #pragma unroll
    for (int i = 0; i < RBLK; i++) {
        mn = fminf(mn, g_part_min[b * RBLK + i]);
        mx = fmaxf(mx, g_part_max[b * RBLK + i]);
    }
    const float range = __fsub_rn(mx, mn);
    const float t = th.t[j];

    unsigned lo = f2ord(mn), hi = f2ord(mx);   // invariant: f(lo) <= t (f(mn)=0)
    while (lo < hi) {
        unsigned mid = lo + ((hi - lo + 1u) >> 1);
        float x = ord2f(mid);
        float norm = __fdiv_rn(__fmul_rn(8.0f, __fsub_rn(x, mn)), range);
        if (norm <= t) lo = mid; else hi = mid - 1u;
    }
    reinterpret_cast<float*>(g_cuts4)[b * 8 + j] = ord2f(lo);
}

// One thread -> 8 output float4 slots (warp-contiguous 512B stores, full
// sectors). Slot s = element (s>>1), time-half (s&1). Streaming stores keep
// the 32MB input L2-resident (loaded by minmax) so encode reads hit L2.
// grid: 8000 blocks x 256 threads; block covers 2048 slots = 1024 elements.
__global__ void __launch_bounds__(256) encode_kernel(const float* __restrict__ in,
                                                     float4* __restrict__ out) {
    const int tid = threadIdx.x;
    const int b   = blockIdx.x / EBLOCKS_PER_B;
    const float4 cut = g_cuts4[b * 2 + (tid & 1)];

    const int base_s = blockIdx.x * 2048 + tid;
    #pragma unroll
    for (int k = 0; k < 8; k++) {
        const int s = base_s + k * 256;
        const float x = __ldg(in + (s >> 1));
        float4 o;
        o.x = (x > cut.x) ? 1.0f : 0.0f;
        o.y = (x > cut.y) ? 1.0f : 0.0f;
        o.z = (x > cut.z) ? 1.0f : 0.0f;
        o.w = (x > cut.w) ? 1.0f : 0.0f;
        __stcs(out + s, o);              // evict-first: don't flush input from L2
    }
}

// ---------------------------------------------------------------------------
// Host: Threefry-2x32, jax.random.permutation(key(1), 8) with
// jax_threefry_partitionable=True semantics (verified rel_err=0, R2/R4/R5/R6):
//   split (foldlike): subkey = threefry(key, (0, 1))
//   random_bits 32-bit: bits_i = out0 ^ out1 of threefry(subkey, (0, i))
// ---------------------------------------------------------------------------
static inline uint32_t rotl32(uint32_t x, int d) { return (x << d) | (x >> (32 - d)); }

static void threefry2x32(uint32_t k0, uint32_t k1, uint32_t x0, uint32_t x1,
                         uint32_t* o0, uint32_t* o1) {
    const int rotA[4] = {13, 15, 26, 6};
    const int rotB[4] = {17, 29, 16, 24};
    uint32_t ks0 = k0, ks1 = k1, ks2 = k0 ^ k1 ^ 0x1BD11BDAu;
    x0 += ks0; x1 += ks1;
    for (int i = 0; i < 4; i++) { x0 += x1; x1 = rotl32(x1, rotA[i]); x1 ^= x0; }
    x0 += ks1; x1 += ks2 + 1u;
    for (int i = 0; i < 4; i++) { x0 += x1; x1 = rotl32(x1, rotB[i]); x1 ^= x0; }
    x0 += ks2; x1 += ks0 + 2u;
    for (int i = 0; i < 4; i++) { x0 += x1; x1 = rotl32(x1, rotA[i]); x1 ^= x0; }
    x0 += ks0; x1 += ks1 + 3u;
    for (int i = 0; i < 4; i++) { x0 += x1; x1 = rotl32(x1, rotB[i]); x1 ^= x0; }
    x0 += ks1; x1 += ks2 + 4u;
    for (int i = 0; i < 4; i++) { x0 += x1; x1 = rotl32(x1, rotA[i]); x1 ^= x0; }
    x0 += ks2; x1 += ks0 + 5u;
    *o0 = x0; *o1 = x1;
}

extern "C" void kernel_launch(void* const* d_in, const int* in_sizes, int n_in,
                              void* d_out, int out_size) {
    uint32_t sk0, sk1;
    threefry2x32(0u, 1u, 0u, 1u, &sk0, &sk1);
    uint32_t keys[8];
    for (int i = 0; i < 8; i++) {
        uint32_t o0, o1;
        threefry2x32(sk0, sk1, 0u, (uint32_t)i, &o0, &o1);
        keys[i] = o0 ^ o1;
    }
    int perm[8] = {0, 1, 2, 3, 4, 5, 6, 7};
    for (int i = 1; i < 8; i++) {           // stable insertion sort (ascending)
        uint32_t kv = keys[perm[i]];
        int p = perm[i], j = i - 1;
        while (j >= 0 && keys[perm[j]] > kv) { perm[j + 1] = perm[j]; j--; }
        perm[j + 1] = p;
    }
    Thresh th;
    for (int i = 0; i < 8; i++) th.t[i] = (float)perm[i];

    const float* in_f = (const float*)d_in[0];

    dim3 rgrid(RBLK, NB);
    minmax_kernel<<<rgrid, 256>>>((const float4*)in_f);
    cuts_kernel<<<1, 512>>>(th);
    encode_kernel<<<NB * EBLOCKS_PER_B, 256>>>(in_f, (float4*)d_out);
}